// round 1
// baseline (speedup 1.0000x reference)
#include <cuda_runtime.h>
#include <math.h>

#define EMBED 1024
#define HEADS 16
#define HDIM  64
#define SEQ   2048
#define BATCH 2
#define MTOT  (BATCH * SEQ)   // 4096 tokens

// ---------------- scratch (device globals; no allocation) ----------------
__device__ float g_q[BATCH * HEADS * SEQ * HDIM];     // [b,h,l,d]
__device__ float g_k[BATCH * HEADS * SEQ * HDIM];
__device__ float g_v[BATCH * HEADS * SEQ * HDIM];
__device__ float g_attn[MTOT * EMBED];                // [b,l,e]

// =====================================================================
// GEMM NT core: C[m,n] = sum_k A[m,k] * B[n,k]
// BM=BN=128, BK=16, 256 threads, 8x8 register tile per thread.
// =====================================================================

__global__ __launch_bounds__(256, 2)
void gemm_qkv_kernel(const float* __restrict__ X,
                     const float* __restrict__ Wq,
                     const float* __restrict__ Wk,
                     const float* __restrict__ Wv)
{
    const int K = EMBED;
    const float* W = (blockIdx.z == 0) ? Wq : (blockIdx.z == 1) ? Wk : Wv;
    float* dst     = (blockIdx.z == 0) ? g_q : (blockIdx.z == 1) ? g_k : g_v;

    const int m0 = blockIdx.y * 128;
    const int n0 = blockIdx.x * 128;

    __shared__ float As[16][132];
    __shared__ float Bs[16][132];

    const int tid = threadIdx.x;
    const int tx = tid & 15;
    const int ty = tid >> 4;
    const int lr = tid >> 2;          // 0..63
    const int lc = (tid & 3) << 2;    // 0,4,8,12

    const float* Aptr = X + (m0 + lr) * K + lc;
    const float* Bptr = W + (n0 + lr) * K + lc;

    float acc[8][8];
    #pragma unroll
    for (int i = 0; i < 8; i++)
        #pragma unroll
        for (int j = 0; j < 8; j++)
            acc[i][j] = 0.0f;

    for (int k0 = 0; k0 < K; k0 += 16) {
        float4 a0 = *(const float4*)(Aptr + k0);
        float4 a1 = *(const float4*)(Aptr + 64 * K + k0);
        float4 b0 = *(const float4*)(Bptr + k0);
        float4 b1 = *(const float4*)(Bptr + 64 * K + k0);

        As[lc + 0][lr]      = a0.x; As[lc + 1][lr]      = a0.y;
        As[lc + 2][lr]      = a0.z; As[lc + 3][lr]      = a0.w;
        As[lc + 0][lr + 64] = a1.x; As[lc + 1][lr + 64] = a1.y;
        As[lc + 2][lr + 64] = a1.z; As[lc + 3][lr + 64] = a1.w;
        Bs[lc + 0][lr]      = b0.x; Bs[lc + 1][lr]      = b0.y;
        Bs[lc + 2][lr]      = b0.z; Bs[lc + 3][lr]      = b0.w;
        Bs[lc + 0][lr + 64] = b1.x; Bs[lc + 1][lr + 64] = b1.y;
        Bs[lc + 2][lr + 64] = b1.z; Bs[lc + 3][lr + 64] = b1.w;
        __syncthreads();

        #pragma unroll
        for (int kk = 0; kk < 16; kk++) {
            float a[8], b[8];
            *(float4*)&a[0] = *(const float4*)&As[kk][ty * 8];
            *(float4*)&a[4] = *(const float4*)&As[kk][ty * 8 + 4];
            *(float4*)&b[0] = *(const float4*)&Bs[kk][tx * 8];
            *(float4*)&b[4] = *(const float4*)&Bs[kk][tx * 8 + 4];
            #pragma unroll
            for (int i = 0; i < 8; i++)
                #pragma unroll
                for (int j = 0; j < 8; j++)
                    acc[i][j] += a[i] * b[j];
        }
        __syncthreads();
    }

    // scatter epilogue: (m,n) -> [b,h,l,d] layout
    #pragma unroll
    for (int i = 0; i < 8; i++) {
        int m = m0 + ty * 8 + i;
        int bb = m >> 11;          // /2048
        int l  = m & 2047;
        #pragma unroll
        for (int j4 = 0; j4 < 8; j4 += 4) {
            int n = n0 + tx * 8 + j4;
            int h = n >> 6;        // /64
            int d = n & 63;
            float4 v = make_float4(acc[i][j4], acc[i][j4 + 1],
                                   acc[i][j4 + 2], acc[i][j4 + 3]);
            *(float4*)&dst[((bb * HEADS + h) * SEQ + l) * HDIM + d] = v;
        }
    }
}

__global__ __launch_bounds__(256, 2)
void gemm_out_kernel(const float* __restrict__ Wo,
                     const float* __restrict__ bias,
                     float* __restrict__ C)
{
    const int K = EMBED;
    const int m0 = blockIdx.y * 128;
    const int n0 = blockIdx.x * 128;

    __shared__ float As[16][132];
    __shared__ float Bs[16][132];

    const int tid = threadIdx.x;
    const int tx = tid & 15;
    const int ty = tid >> 4;
    const int lr = tid >> 2;
    const int lc = (tid & 3) << 2;

    const float* Aptr = g_attn + (m0 + lr) * K + lc;
    const float* Bptr = Wo     + (n0 + lr) * K + lc;

    float acc[8][8];
    #pragma unroll
    for (int i = 0; i < 8; i++)
        #pragma unroll
        for (int j = 0; j < 8; j++)
            acc[i][j] = 0.0f;

    for (int k0 = 0; k0 < K; k0 += 16) {
        float4 a0 = *(const float4*)(Aptr + k0);
        float4 a1 = *(const float4*)(Aptr + 64 * K + k0);
        float4 b0 = *(const float4*)(Bptr + k0);
        float4 b1 = *(const float4*)(Bptr + 64 * K + k0);

        As[lc + 0][lr]      = a0.x; As[lc + 1][lr]      = a0.y;
        As[lc + 2][lr]      = a0.z; As[lc + 3][lr]      = a0.w;
        As[lc + 0][lr + 64] = a1.x; As[lc + 1][lr + 64] = a1.y;
        As[lc + 2][lr + 64] = a1.z; As[lc + 3][lr + 64] = a1.w;
        Bs[lc + 0][lr]      = b0.x; Bs[lc + 1][lr]      = b0.y;
        Bs[lc + 2][lr]      = b0.z; Bs[lc + 3][lr]      = b0.w;
        Bs[lc + 0][lr + 64] = b1.x; Bs[lc + 1][lr + 64] = b1.y;
        Bs[lc + 2][lr + 64] = b1.z; Bs[lc + 3][lr + 64] = b1.w;
        __syncthreads();

        #pragma unroll
        for (int kk = 0; kk < 16; kk++) {
            float a[8], b[8];
            *(float4*)&a[0] = *(const float4*)&As[kk][ty * 8];
            *(float4*)&a[4] = *(const float4*)&As[kk][ty * 8 + 4];
            *(float4*)&b[0] = *(const float4*)&Bs[kk][tx * 8];
            *(float4*)&b[4] = *(const float4*)&Bs[kk][tx * 8 + 4];
            #pragma unroll
            for (int i = 0; i < 8; i++)
                #pragma unroll
                for (int j = 0; j < 8; j++)
                    acc[i][j] += a[i] * b[j];
        }
        __syncthreads();
    }

    #pragma unroll
    for (int i = 0; i < 8; i++) {
        int m = m0 + ty * 8 + i;
        #pragma unroll
        for (int j4 = 0; j4 < 8; j4 += 4) {
            int n = n0 + tx * 8 + j4;
            float4 bv = *(const float4*)&bias[n];
            float4 v = make_float4(acc[i][j4] + bv.x, acc[i][j4 + 1] + bv.y,
                                   acc[i][j4 + 2] + bv.z, acc[i][j4 + 3] + bv.w);
            *(float4*)&C[m * EMBED + n] = v;
        }
    }
}

// =====================================================================
// Flash attention fp32: one block per (qtile=128, head, batch).
// BKV = 64. Online softmax. Writes g_attn in [b,l,e] layout.
// =====================================================================

#define BQ   128
#define BKV  64
#define SSTR 68
#define NTILES (SEQ / BKV)

#define SM_QST   0
#define SM_KST   (SM_QST + 64 * 128)
#define SM_VS    (SM_KST + 64 * 64)
#define SM_SS    (SM_VS + 64 * 64)
#define SM_PT    (SM_SS + 128 * SSTR)
#define SM_ROWM  (SM_PT + 64 * 128)
#define SM_ROWL  (SM_ROWM + 128)
#define SM_ROWF  (SM_ROWL + 128)
#define SM_FLOATS (SM_ROWF + 128)
#define ATTN_SMEM_BYTES (SM_FLOATS * 4)

__global__ __launch_bounds__(256, 1)
void attn_kernel()
{
    extern __shared__ float sm[];
    float* Qst  = sm + SM_QST;    // [d=64][r=128], pre-scaled
    float* Kst  = sm + SM_KST;    // [d=64][j=64]
    float* Vs   = sm + SM_VS;     // [j=64][d=64]
    float* Ss   = sm + SM_SS;     // [r=128][c stride 68]
    float* Pt   = sm + SM_PT;     // [c=64][r=128]
    float* rowm = sm + SM_ROWM;
    float* rowl = sm + SM_ROWL;
    float* rowf = sm + SM_ROWF;

    const int tid = threadIdx.x;
    const int qt = blockIdx.x, h = blockIdx.y, b = blockIdx.z;
    const int q0 = qt * BQ;
    const int headbase = (b * HEADS + h) * SEQ * HDIM;
    const float scale = 0.03125f;  // 1/sqrt(1024)

    // load Q transposed (pre-scaled)
    {
        int r  = tid >> 1;
        int d0 = (tid & 1) * 32;
        const float* src = g_q + headbase + (q0 + r) * HDIM + d0;
        #pragma unroll
        for (int s = 0; s < 8; s++) {
            float4 v = *(const float4*)(src + s * 4);
            Qst[(d0 + s * 4 + 0) * 128 + r] = v.x * scale;
            Qst[(d0 + s * 4 + 1) * 128 + r] = v.y * scale;
            Qst[(d0 + s * 4 + 2) * 128 + r] = v.z * scale;
            Qst[(d0 + s * 4 + 3) * 128 + r] = v.w * scale;
        }
    }
    if (tid < 128) { rowm[tid] = -1e30f; rowl[tid] = 0.0f; }

    const int tx = tid & 15;   // 16 col groups
    const int ty = tid >> 4;   // 16 row groups
    float Oacc[8][4];
    #pragma unroll
    for (int i = 0; i < 8; i++)
        #pragma unroll
        for (int j = 0; j < 4; j++)
            Oacc[i][j] = 0.0f;

    for (int kt = 0; kt < NTILES; kt++) {
        __syncthreads();  // prior phase-4 done with Vs/Pt (and Q load first iter)

        // load K tile transposed + V tile direct
        {
            int j  = tid >> 2;
            int d0 = (tid & 3) * 16;
            const float* ks = g_k + headbase + (kt * BKV + j) * HDIM + d0;
            const float* vs = g_v + headbase + (kt * BKV + j) * HDIM + d0;
            #pragma unroll
            for (int s = 0; s < 4; s++) {
                float4 kv = *(const float4*)(ks + s * 4);
                Kst[(d0 + s * 4 + 0) * 64 + j] = kv.x;
                Kst[(d0 + s * 4 + 1) * 64 + j] = kv.y;
                Kst[(d0 + s * 4 + 2) * 64 + j] = kv.z;
                Kst[(d0 + s * 4 + 3) * 64 + j] = kv.w;
                float4 vv = *(const float4*)(vs + s * 4);
                *(float4*)&Vs[j * 64 + d0 + s * 4] = vv;
            }
        }
        __syncthreads();

        // phase 2: S[128,64] = Qs @ Ks^T (scale pre-applied)
        {
            float sacc[8][4];
            #pragma unroll
            for (int i = 0; i < 8; i++)
                #pragma unroll
                for (int j = 0; j < 4; j++)
                    sacc[i][j] = 0.0f;

            #pragma unroll 8
            for (int d = 0; d < 64; d++) {
                float a[8], bb[4];
                *(float4*)&a[0]  = *(const float4*)&Qst[d * 128 + ty * 8];
                *(float4*)&a[4]  = *(const float4*)&Qst[d * 128 + ty * 8 + 4];
                *(float4*)&bb[0] = *(const float4*)&Kst[d * 64 + tx * 4];
                #pragma unroll
                for (int i = 0; i < 8; i++)
                    #pragma unroll
                    for (int j = 0; j < 4; j++)
                        sacc[i][j] += a[i] * bb[j];
            }
            #pragma unroll
            for (int i = 0; i < 8; i++) {
                float4 v = make_float4(sacc[i][0], sacc[i][1], sacc[i][2], sacc[i][3]);
                *(float4*)&Ss[(ty * 8 + i) * SSTR + tx * 4] = v;
            }
        }
        __syncthreads();

        // phase 3: online softmax; write exp'd P transposed
        {
            int r  = tid >> 1;
            int c0 = (tid & 1) * 32;
            float s[32];
            #pragma unroll
            for (int s4 = 0; s4 < 8; s4++)
                *(float4*)&s[s4 * 4] = *(const float4*)&Ss[r * SSTR + c0 + s4 * 4];

            float mx = s[0];
            #pragma unroll
            for (int c = 1; c < 32; c++) mx = fmaxf(mx, s[c]);
            mx = fmaxf(mx, __shfl_xor_sync(0xffffffffu, mx, 1));

            float m_old = rowm[r];
            float m_new = fmaxf(m_old, mx);
            float f = __expf(m_old - m_new);

            float psum = 0.0f;
            #pragma unroll
            for (int c = 0; c < 32; c++) {
                float p = __expf(s[c] - m_new);
                psum += p;
                Pt[(c0 + c) * 128 + r] = p;
            }
            psum += __shfl_xor_sync(0xffffffffu, psum, 1);

            if ((tid & 1) == 0) {
                rowl[r] = rowl[r] * f + psum;
                rowm[r] = m_new;
                rowf[r] = f;
            }
        }
        __syncthreads();

        // phase 4: O = O*f + P @ V
        {
            float fv[8];
            #pragma unroll
            for (int i = 0; i < 8; i++) fv[i] = rowf[ty * 8 + i];
            #pragma unroll
            for (int i = 0; i < 8; i++)
                #pragma unroll
                for (int j = 0; j < 4; j++)
                    Oacc[i][j] *= fv[i];

            #pragma unroll 8
            for (int j = 0; j < 64; j++) {
                float a[8], bb[4];
                *(float4*)&a[0]  = *(const float4*)&Pt[j * 128 + ty * 8];
                *(float4*)&a[4]  = *(const float4*)&Pt[j * 128 + ty * 8 + 4];
                *(float4*)&bb[0] = *(const float4*)&Vs[j * 64 + tx * 4];
                #pragma unroll
                for (int i = 0; i < 8; i++)
                    #pragma unroll
                    for (int jj = 0; jj < 4; jj++)
                        Oacc[i][jj] += a[i] * bb[jj];
            }
        }
    }

    // epilogue: divide by row sum, write [b,l,e]
    {
        #pragma unroll
        for (int i = 0; i < 8; i++) {
            float inv = 1.0f / rowl[ty * 8 + i];
            float4 o = make_float4(Oacc[i][0] * inv, Oacc[i][1] * inv,
                                   Oacc[i][2] * inv, Oacc[i][3] * inv);
            int m = b * SEQ + q0 + ty * 8 + i;
            *(float4*)&g_attn[m * EMBED + h * HDIM + tx * 4] = o;
        }
    }
}

// =====================================================================
// Launch
// =====================================================================

extern "C" void kernel_launch(void* const* d_in, const int* in_sizes, int n_in,
                              void* d_out, int out_size)
{
    const float* x  = (const float*)d_in[0];
    const float* Wq = (const float*)d_in[1];
    const float* Wk = (const float*)d_in[2];
    const float* Wv = (const float*)d_in[3];
    const float* Wo = (const float*)d_in[4];
    const float* bo = (const float*)d_in[5];
    float* out = (float*)d_out;

    cudaFuncSetAttribute(attn_kernel,
                         cudaFuncAttributeMaxDynamicSharedMemorySize,
                         ATTN_SMEM_BYTES);

    dim3 gqkv(EMBED / 128, MTOT / 128, 3);
    gemm_qkv_kernel<<<gqkv, 256>>>(x, Wq, Wk, Wv);

    dim3 gattn(SEQ / BQ, HEADS, BATCH);
    attn_kernel<<<gattn, 256, ATTN_SMEM_BYTES>>>();

    dim3 gout(EMBED / 128, MTOT / 128, 1);
    gemm_out_kernel<<<gout, 256>>>(Wo, bo, out);
}

// round 2
// speedup vs baseline: 1.0006x; 1.0006x over previous
#include <cuda_runtime.h>
#include <math.h>

#define EMBED 1024
#define HEADS 16
#define HDIM  64
#define SEQ   2048
#define BATCH 2
#define MTOT  (BATCH * SEQ)   // 4096 tokens

// ---------------- scratch (device globals; no allocation) ----------------
__device__ float g_q[BATCH * HEADS * SEQ * HDIM];     // [b,h,l,d]
__device__ float g_k[BATCH * HEADS * SEQ * HDIM];
__device__ float g_v[BATCH * HEADS * SEQ * HDIM];
__device__ float g_attn[MTOT * EMBED];                // [b,l,e]

// =====================================================================
// GEMM NT core: C[m,n] = sum_k A[m,k] * B[n,k]
// BM=BN=128, BK=16, 256 threads, 8x8 register tile per thread.
// =====================================================================

__global__ __launch_bounds__(256, 2)
void gemm_qkv_kernel(const float* __restrict__ X,
                     const float* __restrict__ Wq,
                     const float* __restrict__ Wk,
                     const float* __restrict__ Wv)
{
    const int K = EMBED;
    const float* W = (blockIdx.z == 0) ? Wq : (blockIdx.z == 1) ? Wk : Wv;
    float* dst     = (blockIdx.z == 0) ? g_q : (blockIdx.z == 1) ? g_k : g_v;

    const int m0 = blockIdx.y * 128;
    const int n0 = blockIdx.x * 128;

    __shared__ float As[16][132];
    __shared__ float Bs[16][132];

    const int tid = threadIdx.x;
    const int tx = tid & 15;
    const int ty = tid >> 4;
    const int lr = tid >> 2;          // 0..63
    const int lc = (tid & 3) << 2;    // 0,4,8,12

    const float* Aptr = X + (m0 + lr) * K + lc;
    const float* Bptr = W + (n0 + lr) * K + lc;

    float acc[8][8];
    #pragma unroll
    for (int i = 0; i < 8; i++)
        #pragma unroll
        for (int j = 0; j < 8; j++)
            acc[i][j] = 0.0f;

    for (int k0 = 0; k0 < K; k0 += 16) {
        float4 a0 = *(const float4*)(Aptr + k0);
        float4 a1 = *(const float4*)(Aptr + 64 * K + k0);
        float4 b0 = *(const float4*)(Bptr + k0);
        float4 b1 = *(const float4*)(Bptr + 64 * K + k0);

        As[lc + 0][lr]      = a0.x; As[lc + 1][lr]      = a0.y;
        As[lc + 2][lr]      = a0.z; As[lc + 3][lr]      = a0.w;
        As[lc + 0][lr + 64] = a1.x; As[lc + 1][lr + 64] = a1.y;
        As[lc + 2][lr + 64] = a1.z; As[lc + 3][lr + 64] = a1.w;
        Bs[lc + 0][lr]      = b0.x; Bs[lc + 1][lr]      = b0.y;
        Bs[lc + 2][lr]      = b0.z; Bs[lc + 3][lr]      = b0.w;
        Bs[lc + 0][lr + 64] = b1.x; Bs[lc + 1][lr + 64] = b1.y;
        Bs[lc + 2][lr + 64] = b1.z; Bs[lc + 3][lr + 64] = b1.w;
        __syncthreads();

        #pragma unroll
        for (int kk = 0; kk < 16; kk++) {
            float a[8], b[8];
            *(float4*)&a[0] = *(const float4*)&As[kk][ty * 8];
            *(float4*)&a[4] = *(const float4*)&As[kk][ty * 8 + 4];
            *(float4*)&b[0] = *(const float4*)&Bs[kk][tx * 8];
            *(float4*)&b[4] = *(const float4*)&Bs[kk][tx * 8 + 4];
            #pragma unroll
            for (int i = 0; i < 8; i++)
                #pragma unroll
                for (int j = 0; j < 8; j++)
                    acc[i][j] += a[i] * b[j];
        }
        __syncthreads();
    }

    // scatter epilogue: (m,n) -> [b,h,l,d] layout
    #pragma unroll
    for (int i = 0; i < 8; i++) {
        int m = m0 + ty * 8 + i;
        int bb = m >> 11;          // /2048
        int l  = m & 2047;
        #pragma unroll
        for (int j4 = 0; j4 < 8; j4 += 4) {
            int n = n0 + tx * 8 + j4;
            int h = n >> 6;        // /64
            int d = n & 63;
            float4 v = make_float4(acc[i][j4], acc[i][j4 + 1],
                                   acc[i][j4 + 2], acc[i][j4 + 3]);
            *(float4*)&dst[((bb * HEADS + h) * SEQ + l) * HDIM + d] = v;
        }
    }
}

__global__ __launch_bounds__(256, 2)
void gemm_out_kernel(const float* __restrict__ Wo,
                     const float* __restrict__ bias,
                     float* __restrict__ C)
{
    const int K = EMBED;
    const int m0 = blockIdx.y * 128;
    const int n0 = blockIdx.x * 128;

    __shared__ float As[16][132];
    __shared__ float Bs[16][132];

    const int tid = threadIdx.x;
    const int tx = tid & 15;
    const int ty = tid >> 4;
    const int lr = tid >> 2;
    const int lc = (tid & 3) << 2;

    const float* Aptr = g_attn + (m0 + lr) * K + lc;
    const float* Bptr = Wo     + (n0 + lr) * K + lc;

    float acc[8][8];
    #pragma unroll
    for (int i = 0; i < 8; i++)
        #pragma unroll
        for (int j = 0; j < 8; j++)
            acc[i][j] = 0.0f;

    for (int k0 = 0; k0 < K; k0 += 16) {
        float4 a0 = *(const float4*)(Aptr + k0);
        float4 a1 = *(const float4*)(Aptr + 64 * K + k0);
        float4 b0 = *(const float4*)(Bptr + k0);
        float4 b1 = *(const float4*)(Bptr + 64 * K + k0);

        As[lc + 0][lr]      = a0.x; As[lc + 1][lr]      = a0.y;
        As[lc + 2][lr]      = a0.z; As[lc + 3][lr]      = a0.w;
        As[lc + 0][lr + 64] = a1.x; As[lc + 1][lr + 64] = a1.y;
        As[lc + 2][lr + 64] = a1.z; As[lc + 3][lr + 64] = a1.w;
        Bs[lc + 0][lr]      = b0.x; Bs[lc + 1][lr]      = b0.y;
        Bs[lc + 2][lr]      = b0.z; Bs[lc + 3][lr]      = b0.w;
        Bs[lc + 0][lr + 64] = b1.x; Bs[lc + 1][lr + 64] = b1.y;
        Bs[lc + 2][lr + 64] = b1.z; Bs[lc + 3][lr + 64] = b1.w;
        __syncthreads();

        #pragma unroll
        for (int kk = 0; kk < 16; kk++) {
            float a[8], b[8];
            *(float4*)&a[0] = *(const float4*)&As[kk][ty * 8];
            *(float4*)&a[4] = *(const float4*)&As[kk][ty * 8 + 4];
            *(float4*)&b[0] = *(const float4*)&Bs[kk][tx * 8];
            *(float4*)&b[4] = *(const float4*)&Bs[kk][tx * 8 + 4];
            #pragma unroll
            for (int i = 0; i < 8; i++)
                #pragma unroll
                for (int j = 0; j < 8; j++)
                    acc[i][j] += a[i] * b[j];
        }
        __syncthreads();
    }

    #pragma unroll
    for (int i = 0; i < 8; i++) {
        int m = m0 + ty * 8 + i;
        #pragma unroll
        for (int j4 = 0; j4 < 8; j4 += 4) {
            int n = n0 + tx * 8 + j4;
            float4 bv = *(const float4*)&bias[n];
            float4 v = make_float4(acc[i][j4] + bv.x, acc[i][j4 + 1] + bv.y,
                                   acc[i][j4 + 2] + bv.z, acc[i][j4 + 3] + bv.w);
            *(float4*)&C[m * EMBED + n] = v;
        }
    }
}

// =====================================================================
// Flash attention fp32: one block per (qtile=128, head, batch).
// BKV = 64. Online softmax. Writes g_attn in [b,l,e] layout.
// =====================================================================

#define BQ   128
#define BKV  64
#define SSTR 68
#define NTILES (SEQ / BKV)

#define SM_QST   0
#define SM_KST   (SM_QST + 64 * 128)
#define SM_VS    (SM_KST + 64 * 64)
#define SM_SS    (SM_VS + 64 * 64)
#define SM_PT    (SM_SS + 128 * SSTR)
#define SM_ROWM  (SM_PT + 64 * 128)
#define SM_ROWL  (SM_ROWM + 128)
#define SM_ROWF  (SM_ROWL + 128)
#define SM_FLOATS (SM_ROWF + 128)
#define ATTN_SMEM_BYTES (SM_FLOATS * 4)

__global__ __launch_bounds__(256, 1)
void attn_kernel()
{
    extern __shared__ float sm[];
    float* Qst  = sm + SM_QST;    // [d=64][r=128], pre-scaled
    float* Kst  = sm + SM_KST;    // [d=64][j=64]
    float* Vs   = sm + SM_VS;     // [j=64][d=64]
    float* Ss   = sm + SM_SS;     // [r=128][c stride 68]
    float* Pt   = sm + SM_PT;     // [c=64][r=128]
    float* rowm = sm + SM_ROWM;
    float* rowl = sm + SM_ROWL;
    float* rowf = sm + SM_ROWF;

    const int tid = threadIdx.x;
    const int qt = blockIdx.x, h = blockIdx.y, b = blockIdx.z;
    const int q0 = qt * BQ;
    const int headbase = (b * HEADS + h) * SEQ * HDIM;
    const float scale = 0.03125f;  // 1/sqrt(1024)

    // load Q transposed (pre-scaled)
    {
        int r  = tid >> 1;
        int d0 = (tid & 1) * 32;
        const float* src = g_q + headbase + (q0 + r) * HDIM + d0;
        #pragma unroll
        for (int s = 0; s < 8; s++) {
            float4 v = *(const float4*)(src + s * 4);
            Qst[(d0 + s * 4 + 0) * 128 + r] = v.x * scale;
            Qst[(d0 + s * 4 + 1) * 128 + r] = v.y * scale;
            Qst[(d0 + s * 4 + 2) * 128 + r] = v.z * scale;
            Qst[(d0 + s * 4 + 3) * 128 + r] = v.w * scale;
        }
    }
    if (tid < 128) { rowm[tid] = -1e30f; rowl[tid] = 0.0f; }

    const int tx = tid & 15;   // 16 col groups
    const int ty = tid >> 4;   // 16 row groups
    float Oacc[8][4];
    #pragma unroll
    for (int i = 0; i < 8; i++)
        #pragma unroll
        for (int j = 0; j < 4; j++)
            Oacc[i][j] = 0.0f;

    for (int kt = 0; kt < NTILES; kt++) {
        __syncthreads();  // prior phase-4 done with Vs/Pt (and Q load first iter)

        // load K tile transposed + V tile direct
        {
            int j  = tid >> 2;
            int d0 = (tid & 3) * 16;
            const float* ks = g_k + headbase + (kt * BKV + j) * HDIM + d0;
            const float* vs = g_v + headbase + (kt * BKV + j) * HDIM + d0;
            #pragma unroll
            for (int s = 0; s < 4; s++) {
                float4 kv = *(const float4*)(ks + s * 4);
                Kst[(d0 + s * 4 + 0) * 64 + j] = kv.x;
                Kst[(d0 + s * 4 + 1) * 64 + j] = kv.y;
                Kst[(d0 + s * 4 + 2) * 64 + j] = kv.z;
                Kst[(d0 + s * 4 + 3) * 64 + j] = kv.w;
                float4 vv = *(const float4*)(vs + s * 4);
                *(float4*)&Vs[j * 64 + d0 + s * 4] = vv;
            }
        }
        __syncthreads();

        // phase 2: S[128,64] = Qs @ Ks^T (scale pre-applied)
        {
            float sacc[8][4];
            #pragma unroll
            for (int i = 0; i < 8; i++)
                #pragma unroll
                for (int j = 0; j < 4; j++)
                    sacc[i][j] = 0.0f;

            #pragma unroll 8
            for (int d = 0; d < 64; d++) {
                float a[8], bb[4];
                *(float4*)&a[0]  = *(const float4*)&Qst[d * 128 + ty * 8];
                *(float4*)&a[4]  = *(const float4*)&Qst[d * 128 + ty * 8 + 4];
                *(float4*)&bb[0] = *(const float4*)&Kst[d * 64 + tx * 4];
                #pragma unroll
                for (int i = 0; i < 8; i++)
                    #pragma unroll
                    for (int j = 0; j < 4; j++)
                        sacc[i][j] += a[i] * bb[j];
            }
            #pragma unroll
            for (int i = 0; i < 8; i++) {
                float4 v = make_float4(sacc[i][0], sacc[i][1], sacc[i][2], sacc[i][3]);
                *(float4*)&Ss[(ty * 8 + i) * SSTR + tx * 4] = v;
            }
        }
        __syncthreads();

        // phase 3: online softmax; write exp'd P transposed
        {
            int r  = tid >> 1;
            int c0 = (tid & 1) * 32;
            float s[32];
            #pragma unroll
            for (int s4 = 0; s4 < 8; s4++)
                *(float4*)&s[s4 * 4] = *(const float4*)&Ss[r * SSTR + c0 + s4 * 4];

            float mx = s[0];
            #pragma unroll
            for (int c = 1; c < 32; c++) mx = fmaxf(mx, s[c]);
            mx = fmaxf(mx, __shfl_xor_sync(0xffffffffu, mx, 1));

            float m_old = rowm[r];
            float m_new = fmaxf(m_old, mx);
            float f = __expf(m_old - m_new);

            float psum = 0.0f;
            #pragma unroll
            for (int c = 0; c < 32; c++) {
                float p = __expf(s[c] - m_new);
                psum += p;
                Pt[(c0 + c) * 128 + r] = p;
            }
            psum += __shfl_xor_sync(0xffffffffu, psum, 1);

            if ((tid & 1) == 0) {
                rowl[r] = rowl[r] * f + psum;
                rowm[r] = m_new;
                rowf[r] = f;
            }
        }
        __syncthreads();

        // phase 4: O = O*f + P @ V
        {
            float fv[8];
            #pragma unroll
            for (int i = 0; i < 8; i++) fv[i] = rowf[ty * 8 + i];
            #pragma unroll
            for (int i = 0; i < 8; i++)
                #pragma unroll
                for (int j = 0; j < 4; j++)
                    Oacc[i][j] *= fv[i];

            #pragma unroll 8
            for (int j = 0; j < 64; j++) {
                float a[8], bb[4];
                *(float4*)&a[0]  = *(const float4*)&Pt[j * 128 + ty * 8];
                *(float4*)&a[4]  = *(const float4*)&Pt[j * 128 + ty * 8 + 4];
                *(float4*)&bb[0] = *(const float4*)&Vs[j * 64 + tx * 4];
                #pragma unroll
                for (int i = 0; i < 8; i++)
                    #pragma unroll
                    for (int jj = 0; jj < 4; jj++)
                        Oacc[i][jj] += a[i] * bb[jj];
            }
        }
    }

    // epilogue: divide by row sum, write [b,l,e]
    {
        #pragma unroll
        for (int i = 0; i < 8; i++) {
            float inv = 1.0f / rowl[ty * 8 + i];
            float4 o = make_float4(Oacc[i][0] * inv, Oacc[i][1] * inv,
                                   Oacc[i][2] * inv, Oacc[i][3] * inv);
            int m = b * SEQ + q0 + ty * 8 + i;
            *(float4*)&g_attn[m * EMBED + h * HDIM + tx * 4] = o;
        }
    }
}

// =====================================================================
// Launch
// =====================================================================

extern "C" void kernel_launch(void* const* d_in, const int* in_sizes, int n_in,
                              void* d_out, int out_size)
{
    const float* x  = (const float*)d_in[0];
    const float* Wq = (const float*)d_in[1];
    const float* Wk = (const float*)d_in[2];
    const float* Wv = (const float*)d_in[3];
    const float* Wo = (const float*)d_in[4];
    const float* bo = (const float*)d_in[5];
    float* out = (float*)d_out;

    cudaFuncSetAttribute(attn_kernel,
                         cudaFuncAttributeMaxDynamicSharedMemorySize,
                         ATTN_SMEM_BYTES);

    dim3 gqkv(EMBED / 128, MTOT / 128, 3);
    gemm_qkv_kernel<<<gqkv, 256>>>(x, Wq, Wk, Wv);

    dim3 gattn(SEQ / BQ, HEADS, BATCH);
    attn_kernel<<<gattn, 256, ATTN_SMEM_BYTES>>>();

    dim3 gout(EMBED / 128, MTOT / 128, 1);
    gemm_out_kernel<<<gout, 256>>>(Wo, bo, out);
}

// round 6
// speedup vs baseline: 3.3769x; 3.3750x over previous
#include <cuda_runtime.h>
#include <cuda_bf16.h>
#include <cuda_fp16.h>
#include <stdint.h>
#include <math.h>

#define EMBED 1024
#define HEADS 16
#define HDIM  64
#define SEQ   2048
#define BATCH 2
#define MTOT  (BATCH * SEQ)   // 4096

// ---------------- scratch (device globals; no allocation) ----------------
__device__ __half g_qh[BATCH * HEADS * SEQ * HDIM];   // fp16 [b,h,l,d], pre-scaled by 1/32
__device__ __half g_kh[BATCH * HEADS * SEQ * HDIM];
__device__ __half g_vh[BATCH * HEADS * SEQ * HDIM];
__device__ float g_attn[MTOT * EMBED];                // [b,l,e]

__device__ __nv_bfloat16 g_xh[MTOT * EMBED];
__device__ __nv_bfloat16 g_xl[MTOT * EMBED];
__device__ __nv_bfloat16 g_w3h[3 * EMBED * EMBED];
__device__ __nv_bfloat16 g_w3l[3 * EMBED * EMBED];
__device__ __nv_bfloat16 g_woh[EMBED * EMBED];
__device__ __nv_bfloat16 g_wol[EMBED * EMBED];
__device__ __nv_bfloat16 g_ah[MTOT * EMBED];
__device__ __nv_bfloat16 g_al[MTOT * EMBED];

// =====================================================================
// PTX helpers (baseline sm_80+ instructions only; valid on sm_103 target)
// =====================================================================
__device__ __forceinline__ uint32_t smem_u32(const void* p) {
    uint32_t a;
    asm("{ .reg .u64 t; cvta.to.shared.u64 t, %1; cvt.u32.u64 %0, t; }"
        : "=r"(a) : "l"(p));
    return a;
}

__device__ __forceinline__ void mma_bf16(float* c, const uint32_t* a, const uint32_t* b) {
    asm volatile("mma.sync.aligned.m16n8k16.row.col.f32.bf16.bf16.f32 "
        "{%0,%1,%2,%3}, {%4,%5,%6,%7}, {%8,%9}, {%0,%1,%2,%3};"
        : "+f"(c[0]), "+f"(c[1]), "+f"(c[2]), "+f"(c[3])
        : "r"(a[0]), "r"(a[1]), "r"(a[2]), "r"(a[3]), "r"(b[0]), "r"(b[1]));
}
__device__ __forceinline__ void mma_f16(float* c, const uint32_t* a, const uint32_t* b) {
    asm volatile("mma.sync.aligned.m16n8k16.row.col.f32.f16.f16.f32 "
        "{%0,%1,%2,%3}, {%4,%5,%6,%7}, {%8,%9}, {%0,%1,%2,%3};"
        : "+f"(c[0]), "+f"(c[1]), "+f"(c[2]), "+f"(c[3])
        : "r"(a[0]), "r"(a[1]), "r"(a[2]), "r"(a[3]), "r"(b[0]), "r"(b[1]));
}
__device__ __forceinline__ void ldsm4(uint32_t* r, uint32_t a) {
    asm volatile("ldmatrix.sync.aligned.m8n8.x4.shared.b16 {%0,%1,%2,%3}, [%4];"
        : "=r"(r[0]), "=r"(r[1]), "=r"(r[2]), "=r"(r[3]) : "r"(a));
}
__device__ __forceinline__ void ldsm2(uint32_t* r, uint32_t a) {
    asm volatile("ldmatrix.sync.aligned.m8n8.x2.shared.b16 {%0,%1}, [%2];"
        : "=r"(r[0]), "=r"(r[1]) : "r"(a));
}
__device__ __forceinline__ void ldsm2t(uint32_t* r, uint32_t a) {
    asm volatile("ldmatrix.sync.aligned.m8n8.x2.trans.shared.b16 {%0,%1}, [%2];"
        : "=r"(r[0]), "=r"(r[1]) : "r"(a));
}
#define CP16(dst, src) \
    asm volatile("cp.async.cg.shared.global [%0], [%1], 16;" \
                 :: "r"((uint32_t)(dst)), "l"(src) : "memory")
#define CPCOMMIT() asm volatile("cp.async.commit_group;" ::: "memory")
#define CPWAIT1()  asm volatile("cp.async.wait_group 1;" ::: "memory")

__device__ __forceinline__ uint32_t packh2(float a, float b) {
    __half2 h = __floats2half2_rn(a, b);
    return *reinterpret_cast<uint32_t*>(&h);
}

// =====================================================================
// fp32 -> bf16 hi/lo split
// =====================================================================
__global__ void split_bf16_kernel(const float* __restrict__ src,
                                  __nv_bfloat16* __restrict__ hi,
                                  __nv_bfloat16* __restrict__ lo, int n)
{
    int i = (blockIdx.x * blockDim.x + threadIdx.x) * 4;
    if (i >= n) return;
    float4 v = *(const float4*)(src + i);
    __nv_bfloat16 h0 = __float2bfloat16(v.x);
    __nv_bfloat16 h1 = __float2bfloat16(v.y);
    __nv_bfloat16 h2 = __float2bfloat16(v.z);
    __nv_bfloat16 h3 = __float2bfloat16(v.w);
    __nv_bfloat16 l0 = __float2bfloat16(v.x - __bfloat162float(h0));
    __nv_bfloat16 l1 = __float2bfloat16(v.y - __bfloat162float(h1));
    __nv_bfloat16 l2 = __float2bfloat16(v.z - __bfloat162float(h2));
    __nv_bfloat16 l3 = __float2bfloat16(v.w - __bfloat162float(h3));
    *(__nv_bfloat162*)(hi + i)     = __nv_bfloat162(h0, h1);
    *(__nv_bfloat162*)(hi + i + 2) = __nv_bfloat162(h2, h3);
    *(__nv_bfloat162*)(lo + i)     = __nv_bfloat162(l0, l1);
    *(__nv_bfloat162*)(lo + i + 2) = __nv_bfloat162(l2, l3);
}

// =====================================================================
// mma.sync GEMM NT: C[m,n] = sum_k A[m,k]*B[n,k], bf16 hi/lo (3 mma)
// BM=BN=128, BK=32, 256 threads (8 warps: 2M x 4N), cp.async 2-stage.
// mode 0: fp16 scatter into g_qh/g_kh/g_vh ([b,h,l,d]); Q pre-scaled 1/32
// mode 1: fp32 out + bias
// =====================================================================
#define GSTRIDE 40                       // bf16 elems per smem row (80B)
#define GTS     (128 * GSTRIDE * 2)      // 10240 B per tensor-tile
#define GSTAGE  (4 * GTS)                // 40960 B per stage
#define GSMEM   (2 * GSTAGE)             // 81920 B

__global__ __launch_bounds__(256, 1)
void gemm_mma_kernel(const __nv_bfloat16* __restrict__ Ah,
                     const __nv_bfloat16* __restrict__ Al,
                     const __nv_bfloat16* __restrict__ Bh,
                     const __nv_bfloat16* __restrict__ Bl,
                     float* __restrict__ Cout,
                     const float* __restrict__ bias,
                     int mode)
{
    extern __shared__ char smem[];
    const uint32_t sb = smem_u32(smem);
    const int tid = threadIdx.x;
    const int lane = tid & 31, wid = tid >> 5;
    const int wm = wid & 1, wn = wid >> 1;    // 2 x 4 warp grid
    const int m0 = blockIdx.y * 128, n0 = blockIdx.x * 128;

    // loader: per tensor 512 x 16B units; thread handles rows r0 and r0+64
    const int r0 = tid >> 2, cc = tid & 3;

    const __nv_bfloat16* gsrc[4] = {
        Ah + (size_t)m0 * EMBED, Al + (size_t)m0 * EMBED,
        Bh + (size_t)n0 * EMBED, Bl + (size_t)n0 * EMBED };

    // ldmatrix lane offsets (bytes)
    const uint32_t a_loff = (uint32_t)((lane & 15) * (GSTRIDE * 2)) + (lane >> 4) * 16;
    const uint32_t b_loff = (uint32_t)((lane & 7) * (GSTRIDE * 2)) + ((lane >> 3) & 1) * 16;

    float acc[4][4][4];
    #pragma unroll
    for (int mt = 0; mt < 4; mt++)
        #pragma unroll
        for (int nt = 0; nt < 4; nt++)
            #pragma unroll
            for (int i = 0; i < 4; i++)
                acc[mt][nt][i] = 0.0f;

    // preload chunk 0
    #pragma unroll
    for (int t = 0; t < 4; t++) {
        #pragma unroll
        for (int u = 0; u < 2; u++) {
            int row = r0 + u * 64;
            CP16(sb + t * GTS + row * (GSTRIDE * 2) + cc * 16,
                 gsrc[t] + (size_t)row * EMBED + cc * 8);
        }
    }
    CPCOMMIT();

    for (int c = 0; c < EMBED / 32; c++) {
        if (c + 1 < EMBED / 32) {
            const int k0 = (c + 1) * 32;
            const uint32_t stb = sb + ((c + 1) & 1) * GSTAGE;
            #pragma unroll
            for (int t = 0; t < 4; t++) {
                #pragma unroll
                for (int u = 0; u < 2; u++) {
                    int row = r0 + u * 64;
                    CP16(stb + t * GTS + row * (GSTRIDE * 2) + cc * 16,
                         gsrc[t] + (size_t)row * EMBED + k0 + cc * 8);
                }
            }
        }
        CPCOMMIT();
        CPWAIT1();
        __syncthreads();

        const uint32_t base = sb + (c & 1) * GSTAGE;
        #pragma unroll
        for (int kk = 0; kk < 2; kk++) {
            uint32_t ah[4][4], al[4][4];
            #pragma unroll
            for (int mt = 0; mt < 4; mt++) {
                uint32_t ro = (uint32_t)((wm * 64 + mt * 16) * (GSTRIDE * 2)) + kk * 32 + a_loff;
                ldsm4(ah[mt], base + 0 * GTS + ro);
                ldsm4(al[mt], base + 1 * GTS + ro);
            }
            uint32_t bh[4][2], bl[4][2];
            #pragma unroll
            for (int nt = 0; nt < 4; nt++) {
                uint32_t ro = (uint32_t)((wn * 32 + nt * 8) * (GSTRIDE * 2)) + kk * 32 + b_loff;
                ldsm2(bh[nt], base + 2 * GTS + ro);
                ldsm2(bl[nt], base + 3 * GTS + ro);
            }
            #pragma unroll
            for (int mt = 0; mt < 4; mt++)
                #pragma unroll
                for (int nt = 0; nt < 4; nt++) {
                    mma_bf16(acc[mt][nt], ah[mt], bh[nt]);
                    mma_bf16(acc[mt][nt], ah[mt], bl[nt]);
                    mma_bf16(acc[mt][nt], al[mt], bh[nt]);
                }
        }
        __syncthreads();
    }

    // epilogue
    const int lq = lane >> 2, lr2 = (lane & 3) * 2;
    if (mode == 1) {
        #pragma unroll
        for (int mt = 0; mt < 4; mt++) {
            int m = m0 + wm * 64 + mt * 16 + lq;
            #pragma unroll
            for (int nt = 0; nt < 4; nt++) {
                int n = n0 + wn * 32 + nt * 8 + lr2;
                float2 b2 = *(const float2*)(bias + n);
                float2 vlo = make_float2(acc[mt][nt][0] + b2.x, acc[mt][nt][1] + b2.y);
                float2 vhi = make_float2(acc[mt][nt][2] + b2.x, acc[mt][nt][3] + b2.y);
                *(float2*)(Cout + (size_t)m * EMBED + n) = vlo;
                *(float2*)(Cout + (size_t)(m + 8) * EMBED + n) = vhi;
            }
        }
    } else {
        const int sel = n0 >> 10;
        __half* dst = (sel == 0) ? g_qh : (sel == 1) ? g_kh : g_vh;
        const float sc = (sel == 0) ? 0.03125f : 1.0f;   // Q pre-scale 1/sqrt(1024)
        #pragma unroll
        for (int mt = 0; mt < 4; mt++) {
            int m = m0 + wm * 64 + mt * 16 + lq;
            int bb = m >> 11;
            int l = m & 2047;
            #pragma unroll
            for (int nt = 0; nt < 4; nt++) {
                int ng = n0 + wn * 32 + nt * 8 + lr2;
                int rem = ng & 1023;
                int h = rem >> 6, d = rem & 63;
                __half2 vlo = __floats2half2_rn(acc[mt][nt][0] * sc, acc[mt][nt][1] * sc);
                __half2 vhi = __floats2half2_rn(acc[mt][nt][2] * sc, acc[mt][nt][3] * sc);
                size_t hb = ((size_t)(bb * HEADS + h) * SEQ) * HDIM + d;
                *(__half2*)(dst + hb + (size_t)l * HDIM) = vlo;
                *(__half2*)(dst + hb + (size_t)(l + 8) * HDIM) = vhi;
            }
        }
    }
}

// =====================================================================
// Flash attention, mma.sync fp16. Block = (q-tile 128, head, batch),
// 256 threads (8 warps x 16 q-rows). BKV=64, online softmax in regs.
// =====================================================================
#define ASTRIDE 72                       // fp16 elems per row (144B)
#define ASM_Q   0
#define AQB     (128 * ASTRIDE * 2)      // 18432
#define ASM_K   AQB
#define AKSTAGE (64 * ASTRIDE * 2)       // 9216
#define ASM_V   (ASM_K + 2 * AKSTAGE)
#define ASMEM   (ASM_V + 2 * AKSTAGE)    // 55296

__global__ __launch_bounds__(256)
void attn_mma_kernel()
{
    extern __shared__ char smem[];
    const uint32_t sb = smem_u32(smem);
    const int tid = threadIdx.x, lane = tid & 31, w = tid >> 5;
    const int qt = blockIdx.x, h = blockIdx.y, b = blockIdx.z;
    const size_t hb = (size_t)(b * HEADS + h) * SEQ * HDIM;
    const __half* gq = g_qh + hb + (size_t)qt * 128 * HDIM;
    const __half* gk = g_kh + hb;
    const __half* gv = g_vh + hb;

    const int r = tid >> 2, cc = tid & 3;   // K/V loader: 64 rows x 4 col-units x2

    // issue K/V tile 0 (stage 0)
    CP16(sb + ASM_K + r * 144 + cc * 16,       gk + r * HDIM + cc * 8);
    CP16(sb + ASM_K + r * 144 + (cc + 4) * 16, gk + r * HDIM + cc * 8 + 32);
    CP16(sb + ASM_V + r * 144 + cc * 16,       gv + r * HDIM + cc * 8);
    CP16(sb + ASM_V + r * 144 + (cc + 4) * 16, gv + r * HDIM + cc * 8 + 32);
    CPCOMMIT();

    // copy Q directly (128 rows x 128B)
    {
        int qr = tid >> 1, ub = (tid & 1) * 4;
        #pragma unroll
        for (int i = 0; i < 4; i++) {
            uint4 v = *(const uint4*)(gq + qr * HDIM + (ub + i) * 8);
            *(uint4*)(smem + ASM_Q + qr * 144 + (ub + i) * 16) = v;
        }
    }
    __syncthreads();

    // Q fragments (persist)
    uint32_t qf[4][4];
    {
        uint32_t qaddr = sb + ASM_Q + (uint32_t)((w * 16 + (lane & 15)) * 144) + (lane >> 4) * 16;
        #pragma unroll
        for (int kk = 0; kk < 4; kk++) ldsm4(qf[kk], qaddr + kk * 32);
    }

    float oacc[8][4];
    #pragma unroll
    for (int dt = 0; dt < 8; dt++)
        #pragma unroll
        for (int i = 0; i < 4; i++) oacc[dt][i] = 0.0f;
    float m_lo = -1e30f, m_hi = -1e30f, l_lo = 0.0f, l_hi = 0.0f;

    const uint32_t kfb = sb + ASM_K + (uint32_t)((lane & 7) * 144) + ((lane >> 3) & 1) * 16;
    const uint32_t vfb = sb + ASM_V + (uint32_t)((lane & 15) * 144);

    for (int kt = 0; kt < SEQ / 64; kt++) {
        const uint32_t st = (kt & 1) * AKSTAGE;
        if (kt + 1 < SEQ / 64) {
            const __half* gk2 = gk + (size_t)(kt + 1) * 64 * HDIM;
            const __half* gv2 = gv + (size_t)(kt + 1) * 64 * HDIM;
            const uint32_t st2 = ((kt + 1) & 1) * AKSTAGE;
            CP16(sb + ASM_K + st2 + r * 144 + cc * 16,       gk2 + r * HDIM + cc * 8);
            CP16(sb + ASM_K + st2 + r * 144 + (cc + 4) * 16, gk2 + r * HDIM + cc * 8 + 32);
            CP16(sb + ASM_V + st2 + r * 144 + cc * 16,       gv2 + r * HDIM + cc * 8);
            CP16(sb + ASM_V + st2 + r * 144 + (cc + 4) * 16, gv2 + r * HDIM + cc * 8 + 32);
        }
        CPCOMMIT();
        CPWAIT1();
        __syncthreads();

        // S = Q K^T  (scale pre-applied to Q)
        float sacc[8][4];
        #pragma unroll
        for (int nt = 0; nt < 8; nt++)
            #pragma unroll
            for (int i = 0; i < 4; i++) sacc[nt][i] = 0.0f;
        #pragma unroll
        for (int kk = 0; kk < 4; kk++) {
            #pragma unroll
            for (int nt = 0; nt < 8; nt++) {
                uint32_t kb[2];
                ldsm2(kb, kfb + st + (uint32_t)(nt * 8 * 144) + kk * 32);
                mma_f16(sacc[nt], qf[kk], kb);
            }
        }

        // online softmax (rows exclusive to this warp; quad-lane reduce)
        float tl = sacc[0][0], th = sacc[0][2];
        #pragma unroll
        for (int nt = 0; nt < 8; nt++) {
            tl = fmaxf(tl, fmaxf(sacc[nt][0], sacc[nt][1]));
            th = fmaxf(th, fmaxf(sacc[nt][2], sacc[nt][3]));
        }
        tl = fmaxf(tl, __shfl_xor_sync(0xffffffffu, tl, 1));
        tl = fmaxf(tl, __shfl_xor_sync(0xffffffffu, tl, 2));
        th = fmaxf(th, __shfl_xor_sync(0xffffffffu, th, 1));
        th = fmaxf(th, __shfl_xor_sync(0xffffffffu, th, 2));

        float mn_lo = fmaxf(m_lo, tl), mn_hi = fmaxf(m_hi, th);
        float f_lo = __expf(m_lo - mn_lo), f_hi = __expf(m_hi - mn_hi);
        m_lo = mn_lo; m_hi = mn_hi;

        float ps_lo = 0.0f, ps_hi = 0.0f;
        #pragma unroll
        for (int nt = 0; nt < 8; nt++) {
            sacc[nt][0] = __expf(sacc[nt][0] - mn_lo);
            sacc[nt][1] = __expf(sacc[nt][1] - mn_lo);
            sacc[nt][2] = __expf(sacc[nt][2] - mn_hi);
            sacc[nt][3] = __expf(sacc[nt][3] - mn_hi);
            ps_lo += sacc[nt][0] + sacc[nt][1];
            ps_hi += sacc[nt][2] + sacc[nt][3];
        }
        ps_lo += __shfl_xor_sync(0xffffffffu, ps_lo, 1);
        ps_lo += __shfl_xor_sync(0xffffffffu, ps_lo, 2);
        ps_hi += __shfl_xor_sync(0xffffffffu, ps_hi, 1);
        ps_hi += __shfl_xor_sync(0xffffffffu, ps_hi, 2);
        l_lo = l_lo * f_lo + ps_lo;
        l_hi = l_hi * f_hi + ps_hi;

        // pack P into A-fragments (C-layout -> A-layout, in registers)
        uint32_t af[4][4];
        #pragma unroll
        for (int jt = 0; jt < 4; jt++) {
            af[jt][0] = packh2(sacc[2 * jt][0],     sacc[2 * jt][1]);
            af[jt][1] = packh2(sacc[2 * jt][2],     sacc[2 * jt][3]);
            af[jt][2] = packh2(sacc[2 * jt + 1][0], sacc[2 * jt + 1][1]);
            af[jt][3] = packh2(sacc[2 * jt + 1][2], sacc[2 * jt + 1][3]);
        }

        // rescale O, then O += P V
        #pragma unroll
        for (int dt = 0; dt < 8; dt++) {
            oacc[dt][0] *= f_lo; oacc[dt][1] *= f_lo;
            oacc[dt][2] *= f_hi; oacc[dt][3] *= f_hi;
        }
        #pragma unroll
        for (int dt = 0; dt < 8; dt++) {
            #pragma unroll
            for (int jt = 0; jt < 4; jt++) {
                uint32_t vb[2];
                ldsm2t(vb, vfb + st + (uint32_t)(jt * 16 * 144) + dt * 16);
                mma_f16(oacc[dt], af[jt], vb);
            }
        }
        __syncthreads();
    }

    // epilogue: normalize, write [b,l,e]
    const float inv_lo = 1.0f / l_lo, inv_hi = 1.0f / l_hi;
    const int row_lo = b * SEQ + qt * 128 + w * 16 + (lane >> 2);
    const int e0 = h * HDIM + (lane & 3) * 2;
    #pragma unroll
    for (int dt = 0; dt < 8; dt++) {
        float2 vlo = make_float2(oacc[dt][0] * inv_lo, oacc[dt][1] * inv_lo);
        float2 vhi = make_float2(oacc[dt][2] * inv_hi, oacc[dt][3] * inv_hi);
        *(float2*)(g_attn + (size_t)row_lo * EMBED + e0 + dt * 8) = vlo;
        *(float2*)(g_attn + (size_t)(row_lo + 8) * EMBED + e0 + dt * 8) = vhi;
    }
}

// =====================================================================
// Launch
// =====================================================================
extern "C" void kernel_launch(void* const* d_in, const int* in_sizes, int n_in,
                              void* d_out, int out_size)
{
    const float* x  = (const float*)d_in[0];
    const float* Wq = (const float*)d_in[1];
    const float* Wk = (const float*)d_in[2];
    const float* Wv = (const float*)d_in[3];
    const float* Wo = (const float*)d_in[4];
    const float* bo = (const float*)d_in[5];
    float* out = (float*)d_out;

    cudaFuncSetAttribute(gemm_mma_kernel,
                         cudaFuncAttributeMaxDynamicSharedMemorySize, GSMEM);
    cudaFuncSetAttribute(attn_mma_kernel,
                         cudaFuncAttributeMaxDynamicSharedMemorySize, ASMEM);

    __nv_bfloat16 *xh, *xl, *w3h, *w3l, *woh, *wol, *ah, *al;
    cudaGetSymbolAddress((void**)&xh,  g_xh);
    cudaGetSymbolAddress((void**)&xl,  g_xl);
    cudaGetSymbolAddress((void**)&w3h, g_w3h);
    cudaGetSymbolAddress((void**)&w3l, g_w3l);
    cudaGetSymbolAddress((void**)&woh, g_woh);
    cudaGetSymbolAddress((void**)&wol, g_wol);
    cudaGetSymbolAddress((void**)&ah,  g_ah);
    cudaGetSymbolAddress((void**)&al,  g_al);
    float* attn_f;
    cudaGetSymbolAddress((void**)&attn_f, g_attn);

    const int NX = MTOT * EMBED;       // 4M
    const int NW = EMBED * EMBED;      // 1M

    split_bf16_kernel<<<NX / 1024, 256>>>(x, xh, xl, NX);
    split_bf16_kernel<<<NW / 1024, 256>>>(Wq, w3h, w3l, NW);
    split_bf16_kernel<<<NW / 1024, 256>>>(Wk, w3h + NW, w3l + NW, NW);
    split_bf16_kernel<<<NW / 1024, 256>>>(Wv, w3h + 2 * NW, w3l + 2 * NW, NW);
    split_bf16_kernel<<<NW / 1024, 256>>>(Wo, woh, wol, NW);

    dim3 gqkv(3 * EMBED / 128, MTOT / 128);
    gemm_mma_kernel<<<gqkv, 256, GSMEM>>>(xh, xl, w3h, w3l, nullptr, nullptr, 0);

    dim3 gattn(SEQ / 128, HEADS, BATCH);
    attn_mma_kernel<<<gattn, 256, ASMEM>>>();

    split_bf16_kernel<<<NX / 1024, 256>>>(attn_f, ah, al, NX);

    dim3 gout(EMBED / 128, MTOT / 128);
    gemm_mma_kernel<<<gout, 256, GSMEM>>>(ah, al, woh, wol, out, bo, 1);
}